// round 15
// baseline (speedup 1.0000x reference)
#include <cuda_runtime.h>
#include <cuda_fp16.h>
#include <math.h>
#include <stdint.h>

#define DMODEL 3072
#define NHEAD  24
#define HD     128
#define LQ     1280     // 256 txt + 1024 img queries
#define SKV    4352     // 256 txt + 1024 den + 3072 cached
#define STXT   256

// ---------------- scratch (device globals: allocation-free) ----------------
#define WELEMS ((size_t)DMODEL * DMODEL)
__device__ __half g_Wh[8 * WELEMS];                   // fp16 weights, [K][N]
__device__ __half g_Qp[(size_t)LQ * DMODEL];          // projected Q fp16 (pre-norm)
__device__ __half g_Kp[(size_t)LQ * DMODEL];          // projected K fp16 (pre-norm)
__device__ __half g_Af[(size_t)LQ * DMODEL];          // act fp16 / normed Q / O fp16
__device__ __half g_Ef[(size_t)STXT * DMODEL];        // enc fp16
__device__ __half g_Kf[(size_t)SKV * DMODEL];         // K fp16 (post norm+rope)
__device__ __half g_Vf[(size_t)SKV * DMODEL];         // V fp16

// ---------------- PTX helpers -----------------------------------------------
__device__ __forceinline__ void cp_async16(unsigned dst, const void* src) {
    asm volatile("cp.async.cg.shared.global [%0], [%1], 16;" :: "r"(dst), "l"(src));
}
__device__ __forceinline__ void cp_commit() {
    asm volatile("cp.async.commit_group;");
}
template<int N> __device__ __forceinline__ void cp_wait() {
    asm volatile("cp.async.wait_group %0;" :: "n"(N));
}
__device__ __forceinline__ uint32_t smem_u32(const void* p) {
    uint32_t a;
    asm("{ .reg .u64 t; cvta.to.shared.u64 t, %1; cvt.u32.u64 %0, t; }" : "=r"(a) : "l"(p));
    return a;
}

#define LDSM_X4(r0, r1, r2, r3, addr)                                           \
    asm volatile("ldmatrix.sync.aligned.m8n8.x4.shared.b16 {%0,%1,%2,%3}, [%4];" \
        : "=r"(r0), "=r"(r1), "=r"(r2), "=r"(r3) : "r"(addr))

#define LDSM_X4_T(r0, r1, r2, r3, addr)                                         \
    asm volatile("ldmatrix.sync.aligned.m8n8.x4.trans.shared.b16 {%0,%1,%2,%3}, [%4];" \
        : "=r"(r0), "=r"(r1), "=r"(r2), "=r"(r3) : "r"(addr))

#define MMAH16816(d, a0, a1, a2, a3, b0, b1)                                    \
    asm volatile("mma.sync.aligned.m16n8k16.row.col.f32.f16.f16.f32 "           \
        "{%0,%1,%2,%3},{%4,%5,%6,%7},{%8,%9},{%0,%1,%2,%3};"                    \
        : "+f"((d)[0]), "+f"((d)[1]), "+f"((d)[2]), "+f"((d)[3])                \
        : "r"(a0), "r"(a1), "r"(a2), "r"(a3), "r"(b0), "r"(b1))

__device__ __forceinline__ uint32_t packh(float lo, float hi) {
    __half2 h = __floats2half2_rn(lo, hi);
    return *(uint32_t*)&h;
}

// ---------------- prep: fp32->fp16 conversions, segmented --------------------
struct PrepSet {
    const float* src[8];
    __half* dst[8];
    int n4[8];
};

__global__ void prep(PrepSet p)
{
    const int seg = blockIdx.y;
    const int i = blockIdx.x * 256 + threadIdx.x;
    if (i >= p.n4[seg]) return;
    float4 v = ((const float4*)p.src[seg])[i];
    __half2* H = (__half2*)p.dst[seg];
    H[2 * i]     = __floats2half2_rn(v.x, v.y);
    H[2 * i + 1] = __floats2half2_rn(v.z, v.w);
}

// ---------------- fp16 single-pass GEMM (128x128, trans-B, 4-stage) ----------
struct TGemmSet {
    const __half *a[6];
    const __half *w[6];
    const float* b[6];
    void* c[6];
    int ny[6];
    int hout[6];      // 1 = write fp16, 0 = write fp32
};

#define MG_A_BYTES      (128 * 40 * 2)        // 10240
#define MG_B_OFF        MG_A_BYTES
#define MG_STAGE_BYTES  (MG_A_BYTES + 32 * 136 * 2)   // 18944
#define MG_SMEM         (4 * MG_STAGE_BYTES)          // 75776

__device__ __forceinline__ void mg_load_stage(
    uint32_t sb, int slot,
    const __half* __restrict__ A, const __half* __restrict__ W,
    int m0, int n0, int k0, int t)
{
    const uint32_t s0 = sb + slot * MG_STAGE_BYTES;
#pragma unroll
    for (int c = t; c < 512; c += 256) {
        const int row = c >> 2;
        const int ch  = (c & 3) * 8;
        cp_async16(s0 + (row * 40 + ch) * 2,
                   A + (size_t)(m0 + row) * DMODEL + k0 + ch);
    }
#pragma unroll
    for (int c = t; c < 512; c += 256) {
        const int row = c >> 4;
        const int ch  = (c & 15) * 8;
        cp_async16(s0 + MG_B_OFF + (row * 136 + ch) * 2,
                   W + (size_t)(k0 + row) * DMODEL + n0 + ch);
    }
    cp_commit();
}

__global__ __launch_bounds__(256, 2) void mma_gemm(TGemmSet gs)
{
    extern __shared__ __align__(128) char smg[];
    const uint32_t sb = smem_u32(smg);

    const int z = blockIdx.z;
    if (blockIdx.y >= gs.ny[z]) return;
    const __half* __restrict__ A = gs.a[z];
    const __half* __restrict__ W = gs.w[z];
    const float* __restrict__ bias = gs.b[z];

    const int t    = threadIdx.x;
    const int wid  = t >> 5;
    const int lane = t & 31;
    const int wm   = wid >> 2;
    const int wn   = wid & 3;
    const int m0   = blockIdx.y * 128;
    const int n0   = blockIdx.x * 128;

    const int mat = lane >> 3, r = lane & 7;
    int aOff[4], bOffT[2];
#pragma unroll
    for (int i = 0; i < 4; i++)
        aOff[i] = (wm * 64 + 16 * i + (mat & 1) * 8 + r) * 40 + (mat >> 1) * 8;
    {
        const int tRow = ((mat & 1) << 3) + r;
        const int tCol = (mat >> 1) << 3;
#pragma unroll
        for (int p = 0; p < 2; p++)
            bOffT[p] = tRow * 136 + wn * 32 + 16 * p + tCol;
    }

    float acc[4][4][4];
#pragma unroll
    for (int i = 0; i < 4; i++)
#pragma unroll
        for (int j = 0; j < 4; j++)
#pragma unroll
            for (int q = 0; q < 4; q++) acc[i][j][q] = 0.f;

    const int NS = DMODEL / 32;   // 96
    mg_load_stage(sb, 0, A, W, m0, n0, 0,  t);
    mg_load_stage(sb, 1, A, W, m0, n0, 32, t);
    mg_load_stage(sb, 2, A, W, m0, n0, 64, t);

    for (int s = 0; s < NS; s++) {
        cp_wait<2>();
        __syncthreads();
        const uint32_t s0 = sb + (s & 3) * MG_STAGE_BYTES;

#pragma unroll
        for (int ks = 0; ks < 2; ks++) {
            const int ke = ks * 16;
            uint32_t ah[4][4], bh[2][4];
#pragma unroll
            for (int i = 0; i < 4; i++)
                LDSM_X4(ah[i][0], ah[i][1], ah[i][2], ah[i][3],
                        s0 + (aOff[i] + ke) * 2);
#pragma unroll
            for (int p = 0; p < 2; p++)
                LDSM_X4_T(bh[p][0], bh[p][1], bh[p][2], bh[p][3],
                          s0 + MG_B_OFF + (bOffT[p] + ke * 136) * 2);
#pragma unroll
            for (int i = 0; i < 4; i++)
#pragma unroll
                for (int j = 0; j < 4; j++) {
                    const int p = j >> 1, q = (j & 1) * 2;
                    MMAH16816(acc[i][j], ah[i][0], ah[i][1], ah[i][2], ah[i][3],
                              bh[p][q], bh[p][q + 1]);
                }
        }

        if (s + 3 < NS)
            mg_load_stage(sb, (s + 3) & 3, A, W, m0, n0, (s + 3) * 32, t);
        else
            cp_commit();
    }

    const int r4 = lane >> 2;
    const int c2 = (lane & 3) * 2;
    if (gs.hout[z]) {
        __half* C = (__half*)gs.c[z];
#pragma unroll
        for (int i = 0; i < 4; i++) {
            const int grow = m0 + wm * 64 + 16 * i + r4;
#pragma unroll
            for (int j = 0; j < 4; j++) {
                const int gcol = n0 + wn * 32 + 8 * j + c2;
                const float b0 = bias[gcol], b1 = bias[gcol + 1];
                *(__half2*)(C + (size_t)grow * DMODEL + gcol) =
                    __floats2half2_rn(acc[i][j][0] + b0, acc[i][j][1] + b1);
                *(__half2*)(C + (size_t)(grow + 8) * DMODEL + gcol) =
                    __floats2half2_rn(acc[i][j][2] + b0, acc[i][j][3] + b1);
            }
        }
    } else {
        float* C = (float*)gs.c[z];
#pragma unroll
        for (int i = 0; i < 4; i++) {
            const int grow = m0 + wm * 64 + 16 * i + r4;
#pragma unroll
            for (int j = 0; j < 4; j++) {
                const int gcol = n0 + wn * 32 + 8 * j + c2;
                const float b0 = bias[gcol], b1 = bias[gcol + 1];
                float2 v0, v1;
                v0.x = acc[i][j][0] + b0; v0.y = acc[i][j][1] + b1;
                v1.x = acc[i][j][2] + b0; v1.y = acc[i][j][3] + b1;
                *(float2*)(C + (size_t)grow * DMODEL + gcol)       = v0;
                *(float2*)(C + (size_t)(grow + 8) * DMODEL + gcol) = v1;
            }
        }
    }
}

// ---------------- fused RMSNorm + RoPE for Q and K -> fp16, ONE launch --------
__global__ void normrope_qk(
    const __half* __restrict__ Qp, const __half* __restrict__ Kp,
    const float* __restrict__ ck,
    const float* __restrict__ naqw, const float* __restrict__ nqw,
    const float* __restrict__ nakw, const float* __restrict__ nkw,
    const float* __restrict__ tcos, const float* __restrict__ tsin,
    const float* __restrict__ icos, const float* __restrict__ isin,
    float qscale,
    __half2* __restrict__ Qout, __half2* __restrict__ Kout)
{
    const int id   = blockIdx.x * blockDim.y + threadIdx.y;
    const int lane = threadIdx.x;
    if (id >= (LQ + SKV) * NHEAD) return;
    const int row = id / NHEAD;
    const int h   = id % NHEAD;
    const bool isQ = row < LQ;
    const int rr = isQ ? row : row - LQ;

    float2 v0, v1;
    if (isQ) {
        const __half2* p2 = (const __half2*)(Qp + (size_t)rr * DMODEL + h * HD);
        v0 = __half22float2(p2[lane]);
        v1 = __half22float2(p2[lane + 32]);
    } else if (rr < LQ) {
        const __half2* p2 = (const __half2*)(Kp + (size_t)rr * DMODEL + h * HD);
        v0 = __half22float2(p2[lane]);
        v1 = __half22float2(p2[lane + 32]);
    } else {
        const float2* p2 = (const float2*)(ck + (size_t)(rr - LQ) * DMODEL + h * HD);
        v0 = p2[lane];
        v1 = p2[lane + 32];
    }

    float ss = v0.x * v0.x + v0.y * v0.y + v1.x * v1.x + v1.y * v1.y;
#pragma unroll
    for (int o = 16; o > 0; o >>= 1) ss += __shfl_xor_sync(0xffffffffu, ss, o);
    const float rms = rsqrtf(ss * (1.0f / 128.0f) + 1e-6f);

    const float *w, *cT, *sT;
    if (rr < STXT) {
        w = isQ ? naqw : nakw;
        cT = tcos + (size_t)rr * 64; sT = tsin + (size_t)rr * 64;
    } else {
        w = isQ ? nqw : nkw;
        cT = icos + (size_t)(rr - STXT) * 64; sT = isin + (size_t)(rr - STXT) * 64;
    }
    const float outscale = isQ ? qscale : 1.0f;
    __half2* Hout = isQ ? Qout : Kout;

    const size_t ob = ((size_t)rr * DMODEL + h * HD) / 2;
#pragma unroll
    for (int half = 0; half < 2; half++) {
        const int p = lane + 32 * half;
        const float2 v = half ? v1 : v0;
        float c = cT[p], s = sT[p];
        float yr = v.x * rms * w[2 * p];
        float yi = v.y * rms * w[2 * p + 1];
        float o0 = (yr * c - yi * s) * outscale;
        float o1 = (yr * s + yi * c) * outscale;
        Hout[ob + p] = __floats2half2_rn(o0, o1);
    }
}

// ---------------- Flash attention v7: fp16, 128q x 32kv, Q in smem -----------
#define AQ_BYTES  (128 * 136 * 2)     // 34816: Q tile in smem
#define AKST      (32 * 136 * 2)      // 8704: one K or V 32-row tile
#define AKVSTAGE  (2 * AKST)          // 17408: K+V stage
#define ATTN_SMEM (AQ_BYTES + 2 * AKVSTAGE + 1024)   // 70656
#define ATHREADS  256

__global__ __launch_bounds__(ATHREADS, 2) void attn7(
    const __half* __restrict__ Qf,
    const __half* __restrict__ Kf, const __half* __restrict__ Vf,
    const int* __restrict__ mask,
    __half* __restrict__ O)
{
    extern __shared__ __align__(16) char sm3[];
    const uint32_t sbase  = smem_u32(sm3);
    const uint32_t kvbase = sbase + AQ_BYTES;
    float* mb = (float*)(sm3 + AQ_BYTES + 2 * AKVSTAGE);

    const int t    = threadIdx.x;
    const int wid  = t >> 5;
    const int lane = t & 31;
    const int h    = blockIdx.y;
    const int q0   = blockIdx.x * 128;
    const int hcol = h * HD;

    const int gr = lane >> 2, ct = lane & 3;
    const int mat = lane >> 3, r = lane & 7;
    const int aOffQ = (wid * 16 + (mat & 1) * 8 + r) * 136 + (mat >> 1) * 8;
    const int bRow = ((mat >> 1) << 3) + r;
    const int bCol = (mat & 1) << 3;
    const int vRow = ((mat & 1) << 3) + r;
    const int vCol = (mat >> 1) << 3;

    for (int i = t; i < STXT; i += ATHREADS)
        mb[i] = (mask[i] == 0) ? -1e30f : 0.f;

#pragma unroll
    for (int c = t; c < 2048; c += ATHREADS) {
        const int row = c >> 4;
        const int ch  = (c & 15) * 8;
        cp_async16(sbase + (row * 136 + ch) * 2,
                   Qf + (size_t)(q0 + row) * DMODEL + hcol + ch);
    }

#define ISSUE_KV7(st, kb)                                                         \
    {                                                                             \
        _Pragma("unroll")                                                         \
        for (int c = t; c < 1024; c += ATHREADS) {                                \
            const int mtx = c >> 9;                                               \
            const int rem = c & 511;                                              \
            const int row = rem >> 4;                                             \
            const int ch  = (rem & 15) * 8;                                       \
            const __half* src = mtx ? Vf : Kf;                                    \
            cp_async16(kvbase + (st) * AKVSTAGE + mtx * AKST + (row * 136 + ch) * 2,\
                       src + (size_t)((kb) + row) * DMODEL + hcol + ch);          \
        }                                                                         \
        cp_commit();                                                              \
    }

    ISSUE_KV7(0, 0)

    float o[16][4];
#pragma unroll
    for (int j = 0; j < 16; j++)
#pragma unroll
        for (int e = 0; e < 4; e++) o[j][e] = 0.f;
    float m0 = -INFINITY, m1 = -INFINITY, l0 = 0.f, l1 = 0.f;

    const int NT = SKV / 32;   // 136
    for (int kt = 0; kt < NT; kt++) {
        const int kb = kt * 32;
        if (kt + 1 < NT) {
            ISSUE_KV7((kt + 1) & 1, (kt + 1) * 32)
            cp_wait<1>();
        } else {
            cp_wait<0>();
        }
        __syncthreads();
        const uint32_t stg = kvbase + (kt & 1) * AKVSTAGE;

        float s[4][4];
#pragma unroll
        for (int j = 0; j < 4; j++)
#pragma unroll
            for (int e = 0; e < 4; e++) s[j][e] = 0.f;

#pragma unroll
        for (int c = 0; c < 8; c++) {
            uint32_t qa0, qa1, qa2, qa3;
            LDSM_X4(qa0, qa1, qa2, qa3, sbase + (aOffQ + 16 * c) * 2);
#pragma unroll
            for (int g2 = 0; g2 < 2; g2++) {
                uint32_t k0, k1, k2, k3;
                const uint32_t a = stg +
                    (((g2 * 16 + bRow) * 136 + 16 * c + bCol) << 1);
                LDSM_X4(k0, k1, k2, k3, a);
                MMAH16816(s[2 * g2],     qa0, qa1, qa2, qa3, k0, k1);
                MMAH16816(s[2 * g2 + 1], qa0, qa1, qa2, qa3, k2, k3);
            }
        }

        if (kb < STXT) {
#pragma unroll
            for (int j = 0; j < 4; j++) {
                const int col = kb + 8 * j + 2 * ct;
                const float b0 = mb[col], b1 = mb[col + 1];
                s[j][0] += b0; s[j][1] += b1;
                s[j][2] += b0; s[j][3] += b1;
            }
        }

        float tm0 = -1e30f, tm1 = -1e30f;
#pragma unroll
        for (int j = 0; j < 4; j++) {
            tm0 = fmaxf(tm0, fmaxf(s[j][0], s[j][1]));
            tm1 = fmaxf(tm1, fmaxf(s[j][2], s[j][3]));
        }
        tm0 = fmaxf(tm0, __shfl_xor_sync(0xffffffffu, tm0, 1));
        tm0 = fmaxf(tm0, __shfl_xor_sync(0xffffffffu, tm0, 2));
        tm1 = fmaxf(tm1, __shfl_xor_sync(0xffffffffu, tm1, 1));
        tm1 = fmaxf(tm1, __shfl_xor_sync(0xffffffffu, tm1, 2));
        const float mn0 = fmaxf(m0, tm0), mn1 = fmaxf(m1, tm1);
        if (mn0 != m0 || mn1 != m1) {
            const float c0 = exp2f(m0 - mn0), c1 = exp2f(m1 - mn1);
            l0 *= c0; l1 *= c1;
#pragma unroll
            for (int j = 0; j < 16; j++) {
                o[j][0] *= c0; o[j][1] *= c0;
                o[j][2] *= c1; o[j][3] *= c1;
            }
            m0 = mn0; m1 = mn1;
        }
        float s0 = 0.f, s1 = 0.f;
#pragma unroll
        for (int j = 0; j < 4; j++) {
            s[j][0] = exp2f(s[j][0] - m0);
            s[j][1] = exp2f(s[j][1] - m0);
            s[j][2] = exp2f(s[j][2] - m1);
            s[j][3] = exp2f(s[j][3] - m1);
            s0 += s[j][0] + s[j][1];
            s1 += s[j][2] + s[j][3];
        }
        s0 += __shfl_xor_sync(0xffffffffu, s0, 1);
        s0 += __shfl_xor_sync(0xffffffffu, s0, 2);
        s1 += __shfl_xor_sync(0xffffffffu, s1, 1);
        s1 += __shfl_xor_sync(0xffffffffu, s1, 2);
        l0 += s0; l1 += s1;

        uint32_t ph[2][4];
#pragma unroll
        for (int mm = 0; mm < 2; mm++) {
            const int j0 = 2 * mm, j1 = 2 * mm + 1;
            ph[mm][0] = packh(s[j0][0], s[j0][1]);
            ph[mm][1] = packh(s[j0][2], s[j0][3]);
            ph[mm][2] = packh(s[j1][0], s[j1][1]);
            ph[mm][3] = packh(s[j1][2], s[j1][3]);
        }

#pragma unroll
        for (int mm = 0; mm < 2; mm++) {
#pragma unroll
            for (int g = 0; g < 8; g++) {
                uint32_t v0, v1, v2, v3;
                const uint32_t a = stg + AKST +
                    (((16 * mm + vRow) * 136 + 16 * g + vCol) << 1);
                LDSM_X4_T(v0, v1, v2, v3, a);
                MMAH16816(o[2 * g],     ph[mm][0], ph[mm][1], ph[mm][2], ph[mm][3], v0, v1);
                MMAH16816(o[2 * g + 1], ph[mm][0], ph[mm][1], ph[mm][2], ph[mm][3], v2, v3);
            }
        }
        __syncthreads();
    }
#undef ISSUE_KV7

    const float inv0 = 1.0f / l0, inv1 = 1.0f / l1;
    const size_t r0 = (size_t)(q0 + wid * 16 + gr) * DMODEL + hcol;
    const size_t r1 = r0 + 8 * DMODEL;
#pragma unroll
    for (int j = 0; j < 16; j++) {
        const int col = 8 * j + 2 * ct;
        *(__half2*)(O + r0 + col) = __floats2half2_rn(o[j][0] * inv0, o[j][1] * inv0);
        *(__half2*)(O + r1 + col) = __floats2half2_rn(o[j][2] * inv1, o[j][3] * inv1);
    }
}

// ---------------- launch -----------------------------------------------------
extern "C" void kernel_launch(void* const* d_in, const int* in_sizes, int n_in,
                              void* d_out, int out_size)
{
    const float* hidden = (const float*)d_in[0];
    const float* enc    = (const float*)d_in[1];
    const int*   mask   = (const int*)  d_in[2];
    const float* ck     = (const float*)d_in[3];
    const float* cv     = (const float*)d_in[4];
    const float* icos   = (const float*)d_in[5];
    const float* isin   = (const float*)d_in[6];
    const float* tcos   = (const float*)d_in[7];
    const float* tsin   = (const float*)d_in[8];
    const float* Wq     = (const float*)d_in[9];
    const float* bq     = (const float*)d_in[10];
    const float* Wk     = (const float*)d_in[11];
    const float* bk     = (const float*)d_in[12];
    const float* Wv     = (const float*)d_in[13];
    const float* bv     = (const float*)d_in[14];
    const float* Wq_add = (const float*)d_in[15];
    const float* bq_add = (const float*)d_in[16];
    const float* Wk_add = (const float*)d_in[17];
    const float* bk_add = (const float*)d_in[18];
    const float* Wv_add = (const float*)d_in[19];
    const float* bv_add = (const float*)d_in[20];
    const float* nqw    = (const float*)d_in[21];
    const float* nkw    = (const float*)d_in[22];
    const float* naqw   = (const float*)d_in[23];
    const float* nakw   = (const float*)d_in[24];
    const float* Wo     = (const float*)d_in[25];
    const float* bo     = (const float*)d_in[26];
    const float* Wo_add = (const float*)d_in[27];
    const float* bo_add = (const float*)d_in[28];
    float* out = (float*)d_out;

    __half *Whb, *Qp, *Kp, *Af, *Ef, *Kf, *Vf;
    cudaGetSymbolAddress((void**)&Whb, g_Wh);
    cudaGetSymbolAddress((void**)&Qp, g_Qp);
    cudaGetSymbolAddress((void**)&Kp, g_Kp);
    cudaGetSymbolAddress((void**)&Af, g_Af);
    cudaGetSymbolAddress((void**)&Ef, g_Ef);
    cudaGetSymbolAddress((void**)&Kf, g_Kf);
    cudaGetSymbolAddress((void**)&Vf, g_Vf);

    cudaFuncSetAttribute(mma_gemm, cudaFuncAttributeMaxDynamicSharedMemorySize,
                         MG_SMEM);
    cudaFuncSetAttribute(attn7, cudaFuncAttributeMaxDynamicSharedMemorySize,
                         ATTN_SMEM);

    // side stream + fork/join events (created once; host-side resources only)
    static cudaStream_t s2 = nullptr;
    static cudaEvent_t evFork = nullptr, evJoin = nullptr;
    if (s2 == nullptr) {
        cudaStreamCreateWithFlags(&s2, cudaStreamNonBlocking);
        cudaEventCreateWithFlags(&evFork, cudaEventDisableTiming);
        cudaEventCreateWithFlags(&evJoin, cudaEventDisableTiming);
    }

    // -------- fork: prepB (Wo, Wo_add, cached V) on side stream --------
    cudaEventRecord(evFork, 0);
    cudaStreamWaitEvent(s2, evFork, 0);
    {
        PrepSet p;
        p.src[0] = Wo;     p.dst[0] = Whb + 6 * WELEMS;            p.n4[0] = (int)(WELEMS / 4);
        p.src[1] = Wo_add; p.dst[1] = Whb + 7 * WELEMS;            p.n4[1] = (int)(WELEMS / 4);
        p.src[2] = cv;     p.dst[2] = Vf + (size_t)1280 * DMODEL;  p.n4[2] = 3072 * DMODEL / 4;
        for (int i = 3; i < 8; i++) { p.src[i] = cv; p.dst[i] = Vf; p.n4[i] = 0; }
        prep<<<dim3((int)(WELEMS / 4 / 256), 3), 256, 0, s2>>>(p);
    }
    cudaEventRecord(evJoin, s2);

    // -------- prepA: QKV weights + hidden + enc on main stream --------
    {
        PrepSet p;
        const float* wsrc[6] = { Wq, Wk, Wv, Wq_add, Wk_add, Wv_add };
        for (int i = 0; i < 6; i++) {
            p.src[i] = wsrc[i];
            p.dst[i] = Whb + (size_t)i * WELEMS;
            p.n4[i]  = (int)(WELEMS / 4);
        }
        p.src[6] = hidden; p.dst[6] = Af; p.n4[6] = 1024 * DMODEL / 4;
        p.src[7] = enc;    p.dst[7] = Ef; p.n4[7] = STXT * DMODEL / 4;
        prep<<<dim3((int)(WELEMS / 4 / 256), 8), 256>>>(p);
    }

    // -------- QKV projections: ONE launch, fp16 outputs --------
    {
        TGemmSet g;
        for (int z = 0; z < 3; z++) {
            g.a[z] = Af;
            g.w[z] = Whb + (size_t)z * WELEMS;
            g.ny[z] = 8;
            g.a[z + 3] = Ef;
            g.w[z + 3] = Whb + (size_t)(z + 3) * WELEMS;
            g.ny[z + 3] = 2;
        }
        g.b[0] = bq; g.b[1] = bk; g.b[2] = bv;
        g.b[3] = bq_add; g.b[4] = bk_add; g.b[5] = bv_add;
        g.c[0] = Qp + (size_t)256 * DMODEL;
        g.c[1] = Kp + (size_t)256 * DMODEL;
        g.c[2] = Vf + (size_t)256 * DMODEL;
        g.c[3] = Qp; g.c[4] = Kp; g.c[5] = Vf;
        for (int z = 0; z < 6; z++) g.hout[z] = 1;
        mma_gemm<<<dim3(24, 8, 6), 256, MG_SMEM>>>(g);
    }

    // -------- fused RMSNorm + RoPE for Q and K (one launch) --------
    // qscale = 1/sqrt(128) * log2(e): base-2 softmax domain
    {
        const float qscale = 0.08838834764831845f * 1.4426950408889634f;
        int tot = (LQ + SKV) * NHEAD;
        normrope_qk<<<(tot + 7) / 8, dim3(32, 8)>>>(
            Qp, Kp, ck, naqw, nqw, nakw, nkw,
            tcos, tsin, icos, isin, qscale,
            (__half2*)Af, (__half2*)Kf);
    }

    // -------- join: attention needs cached-V conversion (prepB) --------
    cudaStreamWaitEvent(0, evJoin, 0);

    // -------- attention: Q from Af, O back into Af --------
    attn7<<<dim3(LQ / 128, NHEAD), ATHREADS, ATTN_SMEM>>>(
        Af, Kf, Vf, mask, Af);

    // -------- output projections: ONE launch, fp32 outputs --------
    {
        TGemmSet g;
        g.a[0] = Af + (size_t)256 * DMODEL;
        g.w[0] = Whb + 6 * WELEMS;
        g.b[0] = bo;      g.c[0] = out;
        g.ny[0] = 8;
        g.a[1] = Af;
        g.w[1] = Whb + 7 * WELEMS;
        g.b[1] = bo_add;  g.c[1] = out + (size_t)1024 * DMODEL;
        g.ny[1] = 2;
        for (int z = 2; z < 6; z++) {
            g.a[z] = Af;
            g.w[z] = Whb;
            g.b[z] = bo; g.c[z] = out; g.ny[z] = 0;
        }
        for (int z = 0; z < 6; z++) g.hout[z] = 0;
        mma_gemm<<<dim3(24, 8, 2), 256, MG_SMEM>>>(g);
    }
}

// round 16
// speedup vs baseline: 1.0294x; 1.0294x over previous
#include <cuda_runtime.h>
#include <cuda_fp16.h>
#include <math.h>
#include <stdint.h>

#define DMODEL 3072
#define NHEAD  24
#define HD     128
#define LQ     1280     // 256 txt + 1024 img queries
#define SKV    4352     // 256 txt + 1024 den + 3072 cached
#define STXT   256

// ---------------- scratch (device globals: allocation-free) ----------------
#define WELEMS ((size_t)DMODEL * DMODEL)
__device__ __half g_Wh[8 * WELEMS];                   // fp16 weights, [K][N]
__device__ __half g_Qp[(size_t)LQ * DMODEL];          // projected Q fp16 (pre-norm)
__device__ __half g_Kp[(size_t)LQ * DMODEL];          // projected K fp16 (pre-norm)
__device__ __half g_Af[(size_t)LQ * DMODEL];          // act fp16 / normed Q / O fp16
__device__ __half g_Ef[(size_t)STXT * DMODEL];        // enc fp16
__device__ __half g_Kf[(size_t)SKV * DMODEL];         // K fp16 (post norm+rope)
__device__ __half g_Vf[(size_t)SKV * DMODEL];         // V fp16

// ---------------- PTX helpers -----------------------------------------------
__device__ __forceinline__ void cp_async16(unsigned dst, const void* src) {
    asm volatile("cp.async.cg.shared.global [%0], [%1], 16;" :: "r"(dst), "l"(src));
}
__device__ __forceinline__ void cp_commit() {
    asm volatile("cp.async.commit_group;");
}
template<int N> __device__ __forceinline__ void cp_wait() {
    asm volatile("cp.async.wait_group %0;" :: "n"(N));
}
__device__ __forceinline__ uint32_t smem_u32(const void* p) {
    uint32_t a;
    asm("{ .reg .u64 t; cvta.to.shared.u64 t, %1; cvt.u32.u64 %0, t; }" : "=r"(a) : "l"(p));
    return a;
}

#define LDSM_X4(r0, r1, r2, r3, addr)                                           \
    asm volatile("ldmatrix.sync.aligned.m8n8.x4.shared.b16 {%0,%1,%2,%3}, [%4];" \
        : "=r"(r0), "=r"(r1), "=r"(r2), "=r"(r3) : "r"(addr))

#define LDSM_X4_T(r0, r1, r2, r3, addr)                                         \
    asm volatile("ldmatrix.sync.aligned.m8n8.x4.trans.shared.b16 {%0,%1,%2,%3}, [%4];" \
        : "=r"(r0), "=r"(r1), "=r"(r2), "=r"(r3) : "r"(addr))

#define MMAH16816(d, a0, a1, a2, a3, b0, b1)                                    \
    asm volatile("mma.sync.aligned.m16n8k16.row.col.f32.f16.f16.f32 "           \
        "{%0,%1,%2,%3},{%4,%5,%6,%7},{%8,%9},{%0,%1,%2,%3};"                    \
        : "+f"((d)[0]), "+f"((d)[1]), "+f"((d)[2]), "+f"((d)[3])                \
        : "r"(a0), "r"(a1), "r"(a2), "r"(a3), "r"(b0), "r"(b1))

__device__ __forceinline__ uint32_t packh(float lo, float hi) {
    __half2 h = __floats2half2_rn(lo, hi);
    return *(uint32_t*)&h;
}

// ---------------- prep: all fp32->fp16 conversions in ONE launch -------------
struct PrepSet {
    const float* src[11];
    __half* dst[11];
    int n4[11];
};

__global__ void prep(PrepSet p)
{
    const int seg = blockIdx.y;
    const int i = blockIdx.x * 256 + threadIdx.x;
    if (i >= p.n4[seg]) return;
    float4 v = ((const float4*)p.src[seg])[i];
    __half2* H = (__half2*)p.dst[seg];
    H[2 * i]     = __floats2half2_rn(v.x, v.y);
    H[2 * i + 1] = __floats2half2_rn(v.z, v.w);
}

// ---------------- fp16 single-pass GEMM (128x128, trans-B, 4-stage) ----------
struct TGemmSet {
    const __half *a[6];
    const __half *w[6];
    const float* b[6];
    void* c[6];
    int ny[6];
    int hout[6];      // 1 = write fp16, 0 = write fp32
};

#define MG_A_BYTES      (128 * 40 * 2)        // 10240
#define MG_B_OFF        MG_A_BYTES
#define MG_STAGE_BYTES  (MG_A_BYTES + 32 * 136 * 2)   // 18944
#define MG_SMEM         (4 * MG_STAGE_BYTES)          // 75776

__device__ __forceinline__ void mg_load_stage(
    uint32_t sb, int slot,
    const __half* __restrict__ A, const __half* __restrict__ W,
    int m0, int n0, int k0, int t)
{
    const uint32_t s0 = sb + slot * MG_STAGE_BYTES;
#pragma unroll
    for (int c = t; c < 512; c += 256) {
        const int row = c >> 2;
        const int ch  = (c & 3) * 8;
        cp_async16(s0 + (row * 40 + ch) * 2,
                   A + (size_t)(m0 + row) * DMODEL + k0 + ch);
    }
#pragma unroll
    for (int c = t; c < 512; c += 256) {
        const int row = c >> 4;
        const int ch  = (c & 15) * 8;
        cp_async16(s0 + MG_B_OFF + (row * 136 + ch) * 2,
                   W + (size_t)(k0 + row) * DMODEL + n0 + ch);
    }
    cp_commit();
}

__global__ __launch_bounds__(256, 2) void mma_gemm(TGemmSet gs)
{
    extern __shared__ __align__(128) char smg[];
    const uint32_t sb = smem_u32(smg);

    const int z = blockIdx.z;
    if (blockIdx.y >= gs.ny[z]) return;
    const __half* __restrict__ A = gs.a[z];
    const __half* __restrict__ W = gs.w[z];
    const float* __restrict__ bias = gs.b[z];

    const int t    = threadIdx.x;
    const int wid  = t >> 5;
    const int lane = t & 31;
    const int wm   = wid >> 2;
    const int wn   = wid & 3;
    const int m0   = blockIdx.y * 128;
    const int n0   = blockIdx.x * 128;

    const int mat = lane >> 3, r = lane & 7;
    int aOff[4], bOffT[2];
#pragma unroll
    for (int i = 0; i < 4; i++)
        aOff[i] = (wm * 64 + 16 * i + (mat & 1) * 8 + r) * 40 + (mat >> 1) * 8;
    {
        const int tRow = ((mat & 1) << 3) + r;
        const int tCol = (mat >> 1) << 3;
#pragma unroll
        for (int p = 0; p < 2; p++)
            bOffT[p] = tRow * 136 + wn * 32 + 16 * p + tCol;
    }

    float acc[4][4][4];
#pragma unroll
    for (int i = 0; i < 4; i++)
#pragma unroll
        for (int j = 0; j < 4; j++)
#pragma unroll
            for (int q = 0; q < 4; q++) acc[i][j][q] = 0.f;

    const int NS = DMODEL / 32;   // 96
    mg_load_stage(sb, 0, A, W, m0, n0, 0,  t);
    mg_load_stage(sb, 1, A, W, m0, n0, 32, t);
    mg_load_stage(sb, 2, A, W, m0, n0, 64, t);

    for (int s = 0; s < NS; s++) {
        cp_wait<2>();
        __syncthreads();
        const uint32_t s0 = sb + (s & 3) * MG_STAGE_BYTES;

#pragma unroll
        for (int ks = 0; ks < 2; ks++) {
            const int ke = ks * 16;
            uint32_t ah[4][4], bh[2][4];
#pragma unroll
            for (int i = 0; i < 4; i++)
                LDSM_X4(ah[i][0], ah[i][1], ah[i][2], ah[i][3],
                        s0 + (aOff[i] + ke) * 2);
#pragma unroll
            for (int p = 0; p < 2; p++)
                LDSM_X4_T(bh[p][0], bh[p][1], bh[p][2], bh[p][3],
                          s0 + MG_B_OFF + (bOffT[p] + ke * 136) * 2);
#pragma unroll
            for (int i = 0; i < 4; i++)
#pragma unroll
                for (int j = 0; j < 4; j++) {
                    const int p = j >> 1, q = (j & 1) * 2;
                    MMAH16816(acc[i][j], ah[i][0], ah[i][1], ah[i][2], ah[i][3],
                              bh[p][q], bh[p][q + 1]);
                }
        }

        if (s + 3 < NS)
            mg_load_stage(sb, (s + 3) & 3, A, W, m0, n0, (s + 3) * 32, t);
        else
            cp_commit();
    }

    const int r4 = lane >> 2;
    const int c2 = (lane & 3) * 2;
    if (gs.hout[z]) {
        __half* C = (__half*)gs.c[z];
#pragma unroll
        for (int i = 0; i < 4; i++) {
            const int grow = m0 + wm * 64 + 16 * i + r4;
#pragma unroll
            for (int j = 0; j < 4; j++) {
                const int gcol = n0 + wn * 32 + 8 * j + c2;
                const float b0 = bias[gcol], b1 = bias[gcol + 1];
                *(__half2*)(C + (size_t)grow * DMODEL + gcol) =
                    __floats2half2_rn(acc[i][j][0] + b0, acc[i][j][1] + b1);
                *(__half2*)(C + (size_t)(grow + 8) * DMODEL + gcol) =
                    __floats2half2_rn(acc[i][j][2] + b0, acc[i][j][3] + b1);
            }
        }
    } else {
        float* C = (float*)gs.c[z];
#pragma unroll
        for (int i = 0; i < 4; i++) {
            const int grow = m0 + wm * 64 + 16 * i + r4;
#pragma unroll
            for (int j = 0; j < 4; j++) {
                const int gcol = n0 + wn * 32 + 8 * j + c2;
                const float b0 = bias[gcol], b1 = bias[gcol + 1];
                float2 v0, v1;
                v0.x = acc[i][j][0] + b0; v0.y = acc[i][j][1] + b1;
                v1.x = acc[i][j][2] + b0; v1.y = acc[i][j][3] + b1;
                *(float2*)(C + (size_t)grow * DMODEL + gcol)       = v0;
                *(float2*)(C + (size_t)(grow + 8) * DMODEL + gcol) = v1;
            }
        }
    }
}

// ---------------- fused RMSNorm + RoPE for Q and K -> fp16, ONE launch --------
__global__ void normrope_qk(
    const __half* __restrict__ Qp, const __half* __restrict__ Kp,
    const float* __restrict__ ck,
    const float* __restrict__ naqw, const float* __restrict__ nqw,
    const float* __restrict__ nakw, const float* __restrict__ nkw,
    const float* __restrict__ tcos, const float* __restrict__ tsin,
    const float* __restrict__ icos, const float* __restrict__ isin,
    float qscale,
    __half2* __restrict__ Qout, __half2* __restrict__ Kout)
{
    const int id   = blockIdx.x * blockDim.y + threadIdx.y;
    const int lane = threadIdx.x;
    if (id >= (LQ + SKV) * NHEAD) return;
    const int row = id / NHEAD;
    const int h   = id % NHEAD;
    const bool isQ = row < LQ;
    const int rr = isQ ? row : row - LQ;

    float2 v0, v1;
    if (isQ) {
        const __half2* p2 = (const __half2*)(Qp + (size_t)rr * DMODEL + h * HD);
        v0 = __half22float2(p2[lane]);
        v1 = __half22float2(p2[lane + 32]);
    } else if (rr < LQ) {
        const __half2* p2 = (const __half2*)(Kp + (size_t)rr * DMODEL + h * HD);
        v0 = __half22float2(p2[lane]);
        v1 = __half22float2(p2[lane + 32]);
    } else {
        const float2* p2 = (const float2*)(ck + (size_t)(rr - LQ) * DMODEL + h * HD);
        v0 = p2[lane];
        v1 = p2[lane + 32];
    }

    float ss = v0.x * v0.x + v0.y * v0.y + v1.x * v1.x + v1.y * v1.y;
#pragma unroll
    for (int o = 16; o > 0; o >>= 1) ss += __shfl_xor_sync(0xffffffffu, ss, o);
    const float rms = rsqrtf(ss * (1.0f / 128.0f) + 1e-6f);

    const float *w, *cT, *sT;
    if (rr < STXT) {
        w = isQ ? naqw : nakw;
        cT = tcos + (size_t)rr * 64; sT = tsin + (size_t)rr * 64;
    } else {
        w = isQ ? nqw : nkw;
        cT = icos + (size_t)(rr - STXT) * 64; sT = isin + (size_t)(rr - STXT) * 64;
    }
    const float outscale = isQ ? qscale : 1.0f;
    __half2* Hout = isQ ? Qout : Kout;

    const size_t ob = ((size_t)rr * DMODEL + h * HD) / 2;
#pragma unroll
    for (int half = 0; half < 2; half++) {
        const int p = lane + 32 * half;
        const float2 v = half ? v1 : v0;
        float c = cT[p], s = sT[p];
        float yr = v.x * rms * w[2 * p];
        float yi = v.y * rms * w[2 * p + 1];
        float o0 = (yr * c - yi * s) * outscale;
        float o1 = (yr * s + yi * c) * outscale;
        Hout[ob + p] = __floats2half2_rn(o0, o1);
    }
}

// ---------------- Flash attention v8: fp16, 128q x 32kv, Q smem, 4-stage -----
// One __syncthreads per tile (mma_gemm-style ring: issue kt+3 after compute).
#define AQ_BYTES  (128 * 136 * 2)     // 34816: Q tile in smem
#define AKST      (32 * 136 * 2)      // 8704: one K or V 32-row tile
#define AKVSTAGE  (2 * AKST)          // 17408: K+V stage
#define ANSTAGE   4
#define ATTN_SMEM (AQ_BYTES + ANSTAGE * AKVSTAGE + 1024)   // 105472
#define ATHREADS  256

__global__ __launch_bounds__(ATHREADS, 2) void attn8(
    const __half* __restrict__ Qf,
    const __half* __restrict__ Kf, const __half* __restrict__ Vf,
    const int* __restrict__ mask,
    __half* __restrict__ O)
{
    extern __shared__ __align__(16) char sm3[];
    const uint32_t sbase  = smem_u32(sm3);
    const uint32_t kvbase = sbase + AQ_BYTES;
    float* mb = (float*)(sm3 + AQ_BYTES + ANSTAGE * AKVSTAGE);

    const int t    = threadIdx.x;
    const int wid  = t >> 5;
    const int lane = t & 31;
    const int h    = blockIdx.y;
    const int q0   = blockIdx.x * 128;
    const int hcol = h * HD;

    const int gr = lane >> 2, ct = lane & 3;
    const int mat = lane >> 3, r = lane & 7;
    const int aOffQ = (wid * 16 + (mat & 1) * 8 + r) * 136 + (mat >> 1) * 8;
    const int bRow = ((mat >> 1) << 3) + r;
    const int bCol = (mat & 1) << 3;
    const int vRow = ((mat & 1) << 3) + r;
    const int vCol = (mat >> 1) << 3;

    for (int i = t; i < STXT; i += ATHREADS)
        mb[i] = (mask[i] == 0) ? -1e30f : 0.f;

    // Q tile -> smem (cp.async), grouped with KV stage 0 commit
#pragma unroll
    for (int c = t; c < 2048; c += ATHREADS) {
        const int row = c >> 4;
        const int ch  = (c & 15) * 8;
        cp_async16(sbase + (row * 136 + ch) * 2,
                   Qf + (size_t)(q0 + row) * DMODEL + hcol + ch);
    }

#define ISSUE_KV8(st, kb)                                                         \
    {                                                                             \
        _Pragma("unroll")                                                         \
        for (int c = t; c < 1024; c += ATHREADS) {                                \
            const int mtx = c >> 9;                                               \
            const int rem = c & 511;                                              \
            const int row = rem >> 4;                                             \
            const int ch  = (rem & 15) * 8;                                       \
            const __half* src = mtx ? Vf : Kf;                                    \
            cp_async16(kvbase + (st) * AKVSTAGE + mtx * AKST + (row * 136 + ch) * 2,\
                       src + (size_t)((kb) + row) * DMODEL + hcol + ch);          \
        }                                                                         \
        cp_commit();                                                              \
    }

    const int NT = SKV / 32;   // 136
    ISSUE_KV8(0, 0)            // {Q + KV stage 0}
    ISSUE_KV8(1, 32)
    ISSUE_KV8(2, 64)

    float o[16][4];
#pragma unroll
    for (int j = 0; j < 16; j++)
#pragma unroll
        for (int e = 0; e < 4; e++) o[j][e] = 0.f;
    float m0 = -INFINITY, m1 = -INFINITY, l0 = 0.f, l1 = 0.f;

    for (int kt = 0; kt < NT; kt++) {
        const int kb = kt * 32;
        cp_wait<2>();
        __syncthreads();
        const uint32_t stg = kvbase + (kt & 3) * AKVSTAGE;

        // ---- QK ----
        float s[4][4];
#pragma unroll
        for (int j = 0; j < 4; j++)
#pragma unroll
            for (int e = 0; e < 4; e++) s[j][e] = 0.f;

#pragma unroll
        for (int c = 0; c < 8; c++) {
            uint32_t qa0, qa1, qa2, qa3;
            LDSM_X4(qa0, qa1, qa2, qa3, sbase + (aOffQ + 16 * c) * 2);
#pragma unroll
            for (int g2 = 0; g2 < 2; g2++) {
                uint32_t k0, k1, k2, k3;
                const uint32_t a = stg +
                    (((g2 * 16 + bRow) * 136 + 16 * c + bCol) << 1);
                LDSM_X4(k0, k1, k2, k3, a);
                MMAH16816(s[2 * g2],     qa0, qa1, qa2, qa3, k0, k1);
                MMAH16816(s[2 * g2 + 1], qa0, qa1, qa2, qa3, k2, k3);
            }
        }

        if (kb < STXT) {
#pragma unroll
            for (int j = 0; j < 4; j++) {
                const int col = kb + 8 * j + 2 * ct;
                const float b0 = mb[col], b1 = mb[col + 1];
                s[j][0] += b0; s[j][1] += b1;
                s[j][2] += b0; s[j][3] += b1;
            }
        }

        // ---- online softmax (base-2, conditional rescale) ----
        float tm0 = -1e30f, tm1 = -1e30f;
#pragma unroll
        for (int j = 0; j < 4; j++) {
            tm0 = fmaxf(tm0, fmaxf(s[j][0], s[j][1]));
            tm1 = fmaxf(tm1, fmaxf(s[j][2], s[j][3]));
        }
        tm0 = fmaxf(tm0, __shfl_xor_sync(0xffffffffu, tm0, 1));
        tm0 = fmaxf(tm0, __shfl_xor_sync(0xffffffffu, tm0, 2));
        tm1 = fmaxf(tm1, __shfl_xor_sync(0xffffffffu, tm1, 1));
        tm1 = fmaxf(tm1, __shfl_xor_sync(0xffffffffu, tm1, 2));
        const float mn0 = fmaxf(m0, tm0), mn1 = fmaxf(m1, tm1);
        if (mn0 != m0 || mn1 != m1) {
            const float c0 = exp2f(m0 - mn0), c1 = exp2f(m1 - mn1);
            l0 *= c0; l1 *= c1;
#pragma unroll
            for (int j = 0; j < 16; j++) {
                o[j][0] *= c0; o[j][1] *= c0;
                o[j][2] *= c1; o[j][3] *= c1;
            }
            m0 = mn0; m1 = mn1;
        }
        float s0 = 0.f, s1 = 0.f;
#pragma unroll
        for (int j = 0; j < 4; j++) {
            s[j][0] = exp2f(s[j][0] - m0);
            s[j][1] = exp2f(s[j][1] - m0);
            s[j][2] = exp2f(s[j][2] - m1);
            s[j][3] = exp2f(s[j][3] - m1);
            s0 += s[j][0] + s[j][1];
            s1 += s[j][2] + s[j][3];
        }
        s0 += __shfl_xor_sync(0xffffffffu, s0, 1);
        s0 += __shfl_xor_sync(0xffffffffu, s0, 2);
        s1 += __shfl_xor_sync(0xffffffffu, s1, 1);
        s1 += __shfl_xor_sync(0xffffffffu, s1, 2);
        l0 += s0; l1 += s1;

        // ---- pack P (m16 x k32) to fp16 A-fragments ----
        uint32_t ph[2][4];
#pragma unroll
        for (int mm = 0; mm < 2; mm++) {
            const int j0 = 2 * mm, j1 = 2 * mm + 1;
            ph[mm][0] = packh(s[j0][0], s[j0][1]);
            ph[mm][1] = packh(s[j0][2], s[j0][3]);
            ph[mm][2] = packh(s[j1][0], s[j1][1]);
            ph[mm][3] = packh(s[j1][2], s[j1][3]);
        }

        // ---- PV ----
#pragma unroll
        for (int mm = 0; mm < 2; mm++) {
#pragma unroll
            for (int g = 0; g < 8; g++) {
                uint32_t v0, v1, v2, v3;
                const uint32_t a = stg + AKST +
                    (((16 * mm + vRow) * 136 + 16 * g + vCol) << 1);
                LDSM_X4_T(v0, v1, v2, v3, a);
                MMAH16816(o[2 * g],     ph[mm][0], ph[mm][1], ph[mm][2], ph[mm][3], v0, v1);
                MMAH16816(o[2 * g + 1], ph[mm][0], ph[mm][1], ph[mm][2], ph[mm][3], v2, v3);
            }
        }

        // issue stage kt+3 into slot (kt+3)&3 — holds stage kt-1, whose readers
        // all passed this iteration's __syncthreads (they finished kt-1 first).
        if (kt + 3 < NT)
            ISSUE_KV8((kt + 3) & 3, (kt + 3) * 32)
        else
            cp_commit();   // empty group keeps wait<2> accounting constant
    }
#undef ISSUE_KV8

    const float inv0 = 1.0f / l0, inv1 = 1.0f / l1;
    const size_t r0 = (size_t)(q0 + wid * 16 + gr) * DMODEL + hcol;
    const size_t r1 = r0 + 8 * DMODEL;
#pragma unroll
    for (int j = 0; j < 16; j++) {
        const int col = 8 * j + 2 * ct;
        *(__half2*)(O + r0 + col) = __floats2half2_rn(o[j][0] * inv0, o[j][1] * inv0);
        *(__half2*)(O + r1 + col) = __floats2half2_rn(o[j][2] * inv1, o[j][3] * inv1);
    }
}

// ---------------- launch -----------------------------------------------------
extern "C" void kernel_launch(void* const* d_in, const int* in_sizes, int n_in,
                              void* d_out, int out_size)
{
    const float* hidden = (const float*)d_in[0];
    const float* enc    = (const float*)d_in[1];
    const int*   mask   = (const int*)  d_in[2];
    const float* ck     = (const float*)d_in[3];
    const float* cv     = (const float*)d_in[4];
    const float* icos   = (const float*)d_in[5];
    const float* isin   = (const float*)d_in[6];
    const float* tcos   = (const float*)d_in[7];
    const float* tsin   = (const float*)d_in[8];
    const float* Wq     = (const float*)d_in[9];
    const float* bq     = (const float*)d_in[10];
    const float* Wk     = (const float*)d_in[11];
    const float* bk     = (const float*)d_in[12];
    const float* Wv     = (const float*)d_in[13];
    const float* bv     = (const float*)d_in[14];
    const float* Wq_add = (const float*)d_in[15];
    const float* bq_add = (const float*)d_in[16];
    const float* Wk_add = (const float*)d_in[17];
    const float* bk_add = (const float*)d_in[18];
    const float* Wv_add = (const float*)d_in[19];
    const float* bv_add = (const float*)d_in[20];
    const float* nqw    = (const float*)d_in[21];
    const float* nkw    = (const float*)d_in[22];
    const float* naqw   = (const float*)d_in[23];
    const float* nakw   = (const float*)d_in[24];
    const float* Wo     = (const float*)d_in[25];
    const float* bo     = (const float*)d_in[26];
    const float* Wo_add = (const float*)d_in[27];
    const float* bo_add = (const float*)d_in[28];
    float* out = (float*)d_out;

    __half *Whb, *Qp, *Kp, *Af, *Ef, *Kf, *Vf;
    cudaGetSymbolAddress((void**)&Whb, g_Wh);
    cudaGetSymbolAddress((void**)&Qp, g_Qp);
    cudaGetSymbolAddress((void**)&Kp, g_Kp);
    cudaGetSymbolAddress((void**)&Af, g_Af);
    cudaGetSymbolAddress((void**)&Ef, g_Ef);
    cudaGetSymbolAddress((void**)&Kf, g_Kf);
    cudaGetSymbolAddress((void**)&Vf, g_Vf);

    cudaFuncSetAttribute(mma_gemm, cudaFuncAttributeMaxDynamicSharedMemorySize,
                         MG_SMEM);
    cudaFuncSetAttribute(attn8, cudaFuncAttributeMaxDynamicSharedMemorySize,
                         ATTN_SMEM);

    // -------- prep: ALL fp32->fp16 conversions in one launch --------
    {
        PrepSet p;
        const float* wsrc[8] = { Wq, Wk, Wv, Wq_add, Wk_add, Wv_add, Wo, Wo_add };
        for (int i = 0; i < 8; i++) {
            p.src[i] = wsrc[i];
            p.dst[i] = Whb + (size_t)i * WELEMS;
            p.n4[i]  = (int)(WELEMS / 4);
        }
        p.src[8] = hidden; p.dst[8] = Af;                          p.n4[8] = 1024 * DMODEL / 4;
        p.src[9] = enc;    p.dst[9] = Ef;                          p.n4[9] = STXT * DMODEL / 4;
        p.src[10] = cv;    p.dst[10] = Vf + (size_t)1280 * DMODEL; p.n4[10] = 3072 * DMODEL / 4;
        prep<<<dim3((int)(WELEMS / 4 / 256), 11), 256>>>(p);
    }

    // -------- QKV projections: ONE launch, fp16 outputs --------
    {
        TGemmSet g;
        for (int z = 0; z < 3; z++) {
            g.a[z] = Af;
            g.w[z] = Whb + (size_t)z * WELEMS;
            g.ny[z] = 8;
            g.a[z + 3] = Ef;
            g.w[z + 3] = Whb + (size_t)(z + 3) * WELEMS;
            g.ny[z + 3] = 2;
        }
        g.b[0] = bq; g.b[1] = bk; g.b[2] = bv;
        g.b[3] = bq_add; g.b[4] = bk_add; g.b[5] = bv_add;
        g.c[0] = Qp + (size_t)256 * DMODEL;
        g.c[1] = Kp + (size_t)256 * DMODEL;
        g.c[2] = Vf + (size_t)256 * DMODEL;
        g.c[3] = Qp; g.c[4] = Kp; g.c[5] = Vf;
        for (int z = 0; z < 6; z++) g.hout[z] = 1;
        mma_gemm<<<dim3(24, 8, 6), 256, MG_SMEM>>>(g);
    }

    // -------- fused RMSNorm + RoPE for Q and K (one launch) --------
    // qscale = 1/sqrt(128) * log2(e): base-2 softmax domain
    {
        const float qscale = 0.08838834764831845f * 1.4426950408889634f;
        int tot = (LQ + SKV) * NHEAD;
        normrope_qk<<<(tot + 7) / 8, dim3(32, 8)>>>(
            Qp, Kp, ck, naqw, nqw, nakw, nkw,
            tcos, tsin, icos, isin, qscale,
            (__half2*)Af, (__half2*)Kf);
    }

    // -------- attention: Q from Af, O back into Af --------
    attn8<<<dim3(LQ / 128, NHEAD), ATHREADS, ATTN_SMEM>>>(
        Af, Kf, Vf, mask, Af);

    // -------- output projections: ONE launch, fp32 outputs --------
    {
        TGemmSet g;
        g.a[0] = Af + (size_t)256 * DMODEL;
        g.w[0] = Whb + 6 * WELEMS;
        g.b[0] = bo;      g.c[0] = out;
        g.ny[0] = 8;
        g.a[1] = Af;
        g.w[1] = Whb + 7 * WELEMS;
        g.b[1] = bo_add;  g.c[1] = out + (size_t)1024 * DMODEL;
        g.ny[1] = 2;
        for (int z = 2; z < 6; z++) {
            g.a[z] = Af;
            g.w[z] = Whb;
            g.b[z] = bo; g.c[z] = out; g.ny[z] = 0;
        }
        for (int z = 0; z < 6; z++) g.hout[z] = 0;
        mma_gemm<<<dim3(24, 8, 2), 256, MG_SMEM>>>(g);
    }
}

// round 17
// speedup vs baseline: 1.0669x; 1.0365x over previous
#include <cuda_runtime.h>
#include <cuda_fp16.h>
#include <math.h>
#include <stdint.h>

#define DMODEL 3072
#define NHEAD  24
#define HD     128
#define LQ     1280     // 256 txt + 1024 img queries
#define SKV    4352     // 256 txt + 1024 den + 3072 cached
#define STXT   256

// ---------------- scratch (device globals: allocation-free) ----------------
#define WELEMS ((size_t)DMODEL * DMODEL)
__device__ __half g_Wh[8 * WELEMS];                   // fp16 weights, [K][N]
__device__ __half g_Qp[(size_t)LQ * DMODEL];          // projected Q fp16 (pre-norm)
__device__ __half g_Kp[(size_t)LQ * DMODEL];          // projected K fp16 (pre-norm)
__device__ __half g_Af[(size_t)LQ * DMODEL];          // act fp16 / normed Q / O fp16
__device__ __half g_Ef[(size_t)STXT * DMODEL];        // enc fp16
__device__ __half g_Kf[(size_t)SKV * DMODEL];         // K fp16 (post norm+rope)
__device__ __half g_Vf[(size_t)SKV * DMODEL];         // V fp16

// ---------------- PTX helpers -----------------------------------------------
__device__ __forceinline__ void cp_async16(unsigned dst, const void* src) {
    asm volatile("cp.async.cg.shared.global [%0], [%1], 16;" :: "r"(dst), "l"(src));
}
__device__ __forceinline__ void cp_commit() {
    asm volatile("cp.async.commit_group;");
}
template<int N> __device__ __forceinline__ void cp_wait() {
    asm volatile("cp.async.wait_group %0;" :: "n"(N));
}
__device__ __forceinline__ uint32_t smem_u32(const void* p) {
    uint32_t a;
    asm("{ .reg .u64 t; cvta.to.shared.u64 t, %1; cvt.u32.u64 %0, t; }" : "=r"(a) : "l"(p));
    return a;
}

#define LDSM_X4(r0, r1, r2, r3, addr)                                           \
    asm volatile("ldmatrix.sync.aligned.m8n8.x4.shared.b16 {%0,%1,%2,%3}, [%4];" \
        : "=r"(r0), "=r"(r1), "=r"(r2), "=r"(r3) : "r"(addr))

#define LDSM_X4_T(r0, r1, r2, r3, addr)                                         \
    asm volatile("ldmatrix.sync.aligned.m8n8.x4.trans.shared.b16 {%0,%1,%2,%3}, [%4];" \
        : "=r"(r0), "=r"(r1), "=r"(r2), "=r"(r3) : "r"(addr))

#define MMAH16816(d, a0, a1, a2, a3, b0, b1)                                    \
    asm volatile("mma.sync.aligned.m16n8k16.row.col.f32.f16.f16.f32 "           \
        "{%0,%1,%2,%3},{%4,%5,%6,%7},{%8,%9},{%0,%1,%2,%3};"                    \
        : "+f"((d)[0]), "+f"((d)[1]), "+f"((d)[2]), "+f"((d)[3])                \
        : "r"(a0), "r"(a1), "r"(a2), "r"(a3), "r"(b0), "r"(b1))

__device__ __forceinline__ uint32_t packh(float lo, float hi) {
    __half2 h = __floats2half2_rn(lo, hi);
    return *(uint32_t*)&h;
}

// ---------------- prep: all fp32->fp16 conversions in ONE launch -------------
// 2 float4 per thread for deeper MLP on this pure-bandwidth kernel.
struct PrepSet {
    const float* src[11];
    __half* dst[11];
    int n4[11];
};

__global__ void prep(PrepSet p)
{
    const int seg = blockIdx.y;
    const int base = blockIdx.x * 512 + threadIdx.x;
    const float4* __restrict__ X = (const float4*)p.src[seg];
    __half2* __restrict__ H = (__half2*)p.dst[seg];
    const int n4 = p.n4[seg];
#pragma unroll
    for (int u = 0; u < 2; u++) {
        const int i = base + u * 256;
        if (i < n4) {
            float4 v = X[i];
            H[2 * i]     = __floats2half2_rn(v.x, v.y);
            H[2 * i + 1] = __floats2half2_rn(v.z, v.w);
        }
    }
}

// ---------------- fp16 single-pass GEMM (128x128, trans-B, 4-stage) ----------
struct TGemmSet {
    const __half *a[6];
    const __half *w[6];
    const float* b[6];
    void* c[6];
    int ny[6];
    int hout[6];      // 1 = write fp16, 0 = write fp32
};

#define MG_A_BYTES      (128 * 40 * 2)        // 10240
#define MG_B_OFF        MG_A_BYTES
#define MG_STAGE_BYTES  (MG_A_BYTES + 32 * 136 * 2)   // 18944
#define MG_SMEM         (4 * MG_STAGE_BYTES)          // 75776

__device__ __forceinline__ void mg_load_stage(
    uint32_t sb, int slot,
    const __half* __restrict__ A, const __half* __restrict__ W,
    int m0, int n0, int k0, int t)
{
    const uint32_t s0 = sb + slot * MG_STAGE_BYTES;
#pragma unroll
    for (int c = t; c < 512; c += 256) {
        const int row = c >> 2;
        const int ch  = (c & 3) * 8;
        cp_async16(s0 + (row * 40 + ch) * 2,
                   A + (size_t)(m0 + row) * DMODEL + k0 + ch);
    }
#pragma unroll
    for (int c = t; c < 512; c += 256) {
        const int row = c >> 4;
        const int ch  = (c & 15) * 8;
        cp_async16(s0 + MG_B_OFF + (row * 136 + ch) * 2,
                   W + (size_t)(k0 + row) * DMODEL + n0 + ch);
    }
    cp_commit();
}

__global__ __launch_bounds__(256, 2) void mma_gemm(TGemmSet gs)
{
    extern __shared__ __align__(128) char smg[];
    const uint32_t sb = smem_u32(smg);

    const int z = blockIdx.z;
    if (blockIdx.y >= gs.ny[z]) return;
    const __half* __restrict__ A = gs.a[z];
    const __half* __restrict__ W = gs.w[z];
    const float* __restrict__ bias = gs.b[z];

    const int t    = threadIdx.x;
    const int wid  = t >> 5;
    const int lane = t & 31;
    const int wm   = wid >> 2;
    const int wn   = wid & 3;
    const int m0   = blockIdx.y * 128;
    const int n0   = blockIdx.x * 128;

    const int mat = lane >> 3, r = lane & 7;
    int aOff[4], bOffT[2];
#pragma unroll
    for (int i = 0; i < 4; i++)
        aOff[i] = (wm * 64 + 16 * i + (mat & 1) * 8 + r) * 40 + (mat >> 1) * 8;
    {
        const int tRow = ((mat & 1) << 3) + r;
        const int tCol = (mat >> 1) << 3;
#pragma unroll
        for (int p = 0; p < 2; p++)
            bOffT[p] = tRow * 136 + wn * 32 + 16 * p + tCol;
    }

    float acc[4][4][4];
#pragma unroll
    for (int i = 0; i < 4; i++)
#pragma unroll
        for (int j = 0; j < 4; j++)
#pragma unroll
            for (int q = 0; q < 4; q++) acc[i][j][q] = 0.f;

    const int NS = DMODEL / 32;   // 96
    mg_load_stage(sb, 0, A, W, m0, n0, 0,  t);
    mg_load_stage(sb, 1, A, W, m0, n0, 32, t);
    mg_load_stage(sb, 2, A, W, m0, n0, 64, t);

    for (int s = 0; s < NS; s++) {
        cp_wait<2>();
        __syncthreads();
        const uint32_t s0 = sb + (s & 3) * MG_STAGE_BYTES;

#pragma unroll
        for (int ks = 0; ks < 2; ks++) {
            const int ke = ks * 16;
            uint32_t ah[4][4], bh[2][4];
#pragma unroll
            for (int i = 0; i < 4; i++)
                LDSM_X4(ah[i][0], ah[i][1], ah[i][2], ah[i][3],
                        s0 + (aOff[i] + ke) * 2);
#pragma unroll
            for (int p = 0; p < 2; p++)
                LDSM_X4_T(bh[p][0], bh[p][1], bh[p][2], bh[p][3],
                          s0 + MG_B_OFF + (bOffT[p] + ke * 136) * 2);
#pragma unroll
            for (int i = 0; i < 4; i++)
#pragma unroll
                for (int j = 0; j < 4; j++) {
                    const int p = j >> 1, q = (j & 1) * 2;
                    MMAH16816(acc[i][j], ah[i][0], ah[i][1], ah[i][2], ah[i][3],
                              bh[p][q], bh[p][q + 1]);
                }
        }

        if (s + 3 < NS)
            mg_load_stage(sb, (s + 3) & 3, A, W, m0, n0, (s + 3) * 32, t);
        else
            cp_commit();
    }

    const int r4 = lane >> 2;
    const int c2 = (lane & 3) * 2;
    if (gs.hout[z]) {
        __half* C = (__half*)gs.c[z];
#pragma unroll
        for (int i = 0; i < 4; i++) {
            const int grow = m0 + wm * 64 + 16 * i + r4;
#pragma unroll
            for (int j = 0; j < 4; j++) {
                const int gcol = n0 + wn * 32 + 8 * j + c2;
                const float b0 = bias[gcol], b1 = bias[gcol + 1];
                *(__half2*)(C + (size_t)grow * DMODEL + gcol) =
                    __floats2half2_rn(acc[i][j][0] + b0, acc[i][j][1] + b1);
                *(__half2*)(C + (size_t)(grow + 8) * DMODEL + gcol) =
                    __floats2half2_rn(acc[i][j][2] + b0, acc[i][j][3] + b1);
            }
        }
    } else {
        float* C = (float*)gs.c[z];
#pragma unroll
        for (int i = 0; i < 4; i++) {
            const int grow = m0 + wm * 64 + 16 * i + r4;
#pragma unroll
            for (int j = 0; j < 4; j++) {
                const int gcol = n0 + wn * 32 + 8 * j + c2;
                const float b0 = bias[gcol], b1 = bias[gcol + 1];
                float2 v0, v1;
                v0.x = acc[i][j][0] + b0; v0.y = acc[i][j][1] + b1;
                v1.x = acc[i][j][2] + b0; v1.y = acc[i][j][3] + b1;
                *(float2*)(C + (size_t)grow * DMODEL + gcol)       = v0;
                *(float2*)(C + (size_t)(grow + 8) * DMODEL + gcol) = v1;
            }
        }
    }
}

// ---------------- fused RMSNorm + RoPE for Q and K -> fp16, ONE launch --------
__global__ void normrope_qk(
    const __half* __restrict__ Qp, const __half* __restrict__ Kp,
    const float* __restrict__ ck,
    const float* __restrict__ naqw, const float* __restrict__ nqw,
    const float* __restrict__ nakw, const float* __restrict__ nkw,
    const float* __restrict__ tcos, const float* __restrict__ tsin,
    const float* __restrict__ icos, const float* __restrict__ isin,
    float qscale,
    __half2* __restrict__ Qout, __half2* __restrict__ Kout)
{
    const int id   = blockIdx.x * blockDim.y + threadIdx.y;
    const int lane = threadIdx.x;
    if (id >= (LQ + SKV) * NHEAD) return;
    const int row = id / NHEAD;
    const int h   = id % NHEAD;
    const bool isQ = row < LQ;
    const int rr = isQ ? row : row - LQ;

    float2 v0, v1;
    if (isQ) {
        const __half2* p2 = (const __half2*)(Qp + (size_t)rr * DMODEL + h * HD);
        v0 = __half22float2(p2[lane]);
        v1 = __half22float2(p2[lane + 32]);
    } else if (rr < LQ) {
        const __half2* p2 = (const __half2*)(Kp + (size_t)rr * DMODEL + h * HD);
        v0 = __half22float2(p2[lane]);
        v1 = __half22float2(p2[lane + 32]);
    } else {
        const float2* p2 = (const float2*)(ck + (size_t)(rr - LQ) * DMODEL + h * HD);
        v0 = p2[lane];
        v1 = p2[lane + 32];
    }

    float ss = v0.x * v0.x + v0.y * v0.y + v1.x * v1.x + v1.y * v1.y;
#pragma unroll
    for (int o = 16; o > 0; o >>= 1) ss += __shfl_xor_sync(0xffffffffu, ss, o);
    const float rms = rsqrtf(ss * (1.0f / 128.0f) + 1e-6f);

    const float *w, *cT, *sT;
    if (rr < STXT) {
        w = isQ ? naqw : nakw;
        cT = tcos + (size_t)rr * 64; sT = tsin + (size_t)rr * 64;
    } else {
        w = isQ ? nqw : nkw;
        cT = icos + (size_t)(rr - STXT) * 64; sT = isin + (size_t)(rr - STXT) * 64;
    }
    const float outscale = isQ ? qscale : 1.0f;
    __half2* Hout = isQ ? Qout : Kout;

    const size_t ob = ((size_t)rr * DMODEL + h * HD) / 2;
#pragma unroll
    for (int half = 0; half < 2; half++) {
        const int p = lane + 32 * half;
        const float2 v = half ? v1 : v0;
        float c = cT[p], s = sT[p];
        float yr = v.x * rms * w[2 * p];
        float yi = v.y * rms * w[2 * p + 1];
        float o0 = (yr * c - yi * s) * outscale;
        float o1 = (yr * s + yi * c) * outscale;
        Hout[ob + p] = __floats2half2_rn(o0, o1);
    }
}

// ---------------- Flash attention v9: fp16, 128q x 32kv, Q smem, 4-stage -----
// Single sync/tile; stage kt+3 issued BEFORE the PV loop for deeper overlap.
#define AQ_BYTES  (128 * 136 * 2)     // 34816: Q tile in smem
#define AKST      (32 * 136 * 2)      // 8704: one K or V 32-row tile
#define AKVSTAGE  (2 * AKST)          // 17408: K+V stage
#define ANSTAGE   4
#define ATTN_SMEM (AQ_BYTES + ANSTAGE * AKVSTAGE + 1024)   // 105472
#define ATHREADS  256

__global__ __launch_bounds__(ATHREADS, 2) void attn9(
    const __half* __restrict__ Qf,
    const __half* __restrict__ Kf, const __half* __restrict__ Vf,
    const int* __restrict__ mask,
    __half* __restrict__ O)
{
    extern __shared__ __align__(16) char sm3[];
    const uint32_t sbase  = smem_u32(sm3);
    const uint32_t kvbase = sbase + AQ_BYTES;
    float* mb = (float*)(sm3 + AQ_BYTES + ANSTAGE * AKVSTAGE);

    const int t    = threadIdx.x;
    const int wid  = t >> 5;
    const int lane = t & 31;
    const int h    = blockIdx.y;
    const int q0   = blockIdx.x * 128;
    const int hcol = h * HD;

    const int gr = lane >> 2, ct = lane & 3;
    const int mat = lane >> 3, r = lane & 7;
    const int aOffQ = (wid * 16 + (mat & 1) * 8 + r) * 136 + (mat >> 1) * 8;
    const int bRow = ((mat >> 1) << 3) + r;
    const int bCol = (mat & 1) << 3;
    const int vRow = ((mat & 1) << 3) + r;
    const int vCol = (mat >> 1) << 3;

    for (int i = t; i < STXT; i += ATHREADS)
        mb[i] = (mask[i] == 0) ? -1e30f : 0.f;

    // Q tile -> smem (cp.async), grouped with KV stage 0 commit
#pragma unroll
    for (int c = t; c < 2048; c += ATHREADS) {
        const int row = c >> 4;
        const int ch  = (c & 15) * 8;
        cp_async16(sbase + (row * 136 + ch) * 2,
                   Qf + (size_t)(q0 + row) * DMODEL + hcol + ch);
    }

#define ISSUE_KV9(st, kb)                                                         \
    {                                                                             \
        _Pragma("unroll")                                                         \
        for (int c = t; c < 1024; c += ATHREADS) {                                \
            const int mtx = c >> 9;                                               \
            const int rem = c & 511;                                              \
            const int row = rem >> 4;                                             \
            const int ch  = (rem & 15) * 8;                                       \
            const __half* src = mtx ? Vf : Kf;                                    \
            cp_async16(kvbase + (st) * AKVSTAGE + mtx * AKST + (row * 136 + ch) * 2,\
                       src + (size_t)((kb) + row) * DMODEL + hcol + ch);          \
        }                                                                         \
        cp_commit();                                                              \
    }

    const int NT = SKV / 32;   // 136
    ISSUE_KV9(0, 0)            // {Q + KV stage 0}
    ISSUE_KV9(1, 32)
    ISSUE_KV9(2, 64)

    float o[16][4];
#pragma unroll
    for (int j = 0; j < 16; j++)
#pragma unroll
        for (int e = 0; e < 4; e++) o[j][e] = 0.f;
    float m0 = -INFINITY, m1 = -INFINITY, l0 = 0.f, l1 = 0.f;

    for (int kt = 0; kt < NT; kt++) {
        const int kb = kt * 32;
        cp_wait<2>();
        __syncthreads();
        const uint32_t stg = kvbase + (kt & 3) * AKVSTAGE;

        // ---- QK ----
        float s[4][4];
#pragma unroll
        for (int j = 0; j < 4; j++)
#pragma unroll
            for (int e = 0; e < 4; e++) s[j][e] = 0.f;

#pragma unroll
        for (int c = 0; c < 8; c++) {
            uint32_t qa0, qa1, qa2, qa3;
            LDSM_X4(qa0, qa1, qa2, qa3, sbase + (aOffQ + 16 * c) * 2);
#pragma unroll
            for (int g2 = 0; g2 < 2; g2++) {
                uint32_t k0, k1, k2, k3;
                const uint32_t a = stg +
                    (((g2 * 16 + bRow) * 136 + 16 * c + bCol) << 1);
                LDSM_X4(k0, k1, k2, k3, a);
                MMAH16816(s[2 * g2],     qa0, qa1, qa2, qa3, k0, k1);
                MMAH16816(s[2 * g2 + 1], qa0, qa1, qa2, qa3, k2, k3);
            }
        }

        if (kb < STXT) {
#pragma unroll
            for (int j = 0; j < 4; j++) {
                const int col = kb + 8 * j + 2 * ct;
                const float b0 = mb[col], b1 = mb[col + 1];
                s[j][0] += b0; s[j][1] += b1;
                s[j][2] += b0; s[j][3] += b1;
            }
        }

        // ---- online softmax (base-2, conditional rescale) ----
        float tm0 = -1e30f, tm1 = -1e30f;
#pragma unroll
        for (int j = 0; j < 4; j++) {
            tm0 = fmaxf(tm0, fmaxf(s[j][0], s[j][1]));
            tm1 = fmaxf(tm1, fmaxf(s[j][2], s[j][3]));
        }
        tm0 = fmaxf(tm0, __shfl_xor_sync(0xffffffffu, tm0, 1));
        tm0 = fmaxf(tm0, __shfl_xor_sync(0xffffffffu, tm0, 2));
        tm1 = fmaxf(tm1, __shfl_xor_sync(0xffffffffu, tm1, 1));
        tm1 = fmaxf(tm1, __shfl_xor_sync(0xffffffffu, tm1, 2));
        const float mn0 = fmaxf(m0, tm0), mn1 = fmaxf(m1, tm1);
        if (mn0 != m0 || mn1 != m1) {
            const float c0 = exp2f(m0 - mn0), c1 = exp2f(m1 - mn1);
            l0 *= c0; l1 *= c1;
#pragma unroll
            for (int j = 0; j < 16; j++) {
                o[j][0] *= c0; o[j][1] *= c0;
                o[j][2] *= c1; o[j][3] *= c1;
            }
            m0 = mn0; m1 = mn1;
        }
        float s0 = 0.f, s1 = 0.f;
#pragma unroll
        for (int j = 0; j < 4; j++) {
            s[j][0] = exp2f(s[j][0] - m0);
            s[j][1] = exp2f(s[j][1] - m0);
            s[j][2] = exp2f(s[j][2] - m1);
            s[j][3] = exp2f(s[j][3] - m1);
            s0 += s[j][0] + s[j][1];
            s1 += s[j][2] + s[j][3];
        }
        s0 += __shfl_xor_sync(0xffffffffu, s0, 1);
        s0 += __shfl_xor_sync(0xffffffffu, s0, 2);
        s1 += __shfl_xor_sync(0xffffffffu, s1, 1);
        s1 += __shfl_xor_sync(0xffffffffu, s1, 2);
        l0 += s0; l1 += s1;

        // ---- pack P (m16 x k32) to fp16 A-fragments ----
        uint32_t ph[2][4];
#pragma unroll
        for (int mm = 0; mm < 2; mm++) {
            const int j0 = 2 * mm, j1 = 2 * mm + 1;
            ph[mm][0] = packh(s[j0][0], s[j0][1]);
            ph[mm][1] = packh(s[j0][2], s[j0][3]);
            ph[mm][2] = packh(s[j1][0], s[j1][1]);
            ph[mm][3] = packh(s[j1][2], s[j1][3]);
        }

        // issue stage kt+3 BEFORE PV: slot (kt+3)&3 holds stage kt-1, which
        // every warp finished before passing this iteration's __syncthreads.
        if (kt + 3 < NT)
            ISSUE_KV9((kt + 3) & 3, (kt + 3) * 32)
        else
            cp_commit();   // empty group keeps wait<2> accounting constant

        // ---- PV ----
#pragma unroll
        for (int mm = 0; mm < 2; mm++) {
#pragma unroll
            for (int g = 0; g < 8; g++) {
                uint32_t v0, v1, v2, v3;
                const uint32_t a = stg + AKST +
                    (((16 * mm + vRow) * 136 + 16 * g + vCol) << 1);
                LDSM_X4_T(v0, v1, v2, v3, a);
                MMAH16816(o[2 * g],     ph[mm][0], ph[mm][1], ph[mm][2], ph[mm][3], v0, v1);
                MMAH16816(o[2 * g + 1], ph[mm][0], ph[mm][1], ph[mm][2], ph[mm][3], v2, v3);
            }
        }
    }
#undef ISSUE_KV9

    const float inv0 = 1.0f / l0, inv1 = 1.0f / l1;
    const size_t r0 = (size_t)(q0 + wid * 16 + gr) * DMODEL + hcol;
    const size_t r1 = r0 + 8 * DMODEL;
#pragma unroll
    for (int j = 0; j < 16; j++) {
        const int col = 8 * j + 2 * ct;
        *(__half2*)(O + r0 + col) = __floats2half2_rn(o[j][0] * inv0, o[j][1] * inv0);
        *(__half2*)(O + r1 + col) = __floats2half2_rn(o[j][2] * inv1, o[j][3] * inv1);
    }
}

// ---------------- launch -----------------------------------------------------
extern "C" void kernel_launch(void* const* d_in, const int* in_sizes, int n_in,
                              void* d_out, int out_size)
{
    const float* hidden = (const float*)d_in[0];
    const float* enc    = (const float*)d_in[1];
    const int*   mask   = (const int*)  d_in[2];
    const float* ck     = (const float*)d_in[3];
    const float* cv     = (const float*)d_in[4];
    const float* icos   = (const float*)d_in[5];
    const float* isin   = (const float*)d_in[6];
    const float* tcos   = (const float*)d_in[7];
    const float* tsin   = (const float*)d_in[8];
    const float* Wq     = (const float*)d_in[9];
    const float* bq     = (const float*)d_in[10];
    const float* Wk     = (const float*)d_in[11];
    const float* bk     = (const float*)d_in[12];
    const float* Wv     = (const float*)d_in[13];
    const float* bv     = (const float*)d_in[14];
    const float* Wq_add = (const float*)d_in[15];
    const float* bq_add = (const float*)d_in[16];
    const float* Wk_add = (const float*)d_in[17];
    const float* bk_add = (const float*)d_in[18];
    const float* Wv_add = (const float*)d_in[19];
    const float* bv_add = (const float*)d_in[20];
    const float* nqw    = (const float*)d_in[21];
    const float* nkw    = (const float*)d_in[22];
    const float* naqw   = (const float*)d_in[23];
    const float* nakw   = (const float*)d_in[24];
    const float* Wo     = (const float*)d_in[25];
    const float* bo     = (const float*)d_in[26];
    const float* Wo_add = (const float*)d_in[27];
    const float* bo_add = (const float*)d_in[28];
    float* out = (float*)d_out;

    __half *Whb, *Qp, *Kp, *Af, *Ef, *Kf, *Vf;
    cudaGetSymbolAddress((void**)&Whb, g_Wh);
    cudaGetSymbolAddress((void**)&Qp, g_Qp);
    cudaGetSymbolAddress((void**)&Kp, g_Kp);
    cudaGetSymbolAddress((void**)&Af, g_Af);
    cudaGetSymbolAddress((void**)&Ef, g_Ef);
    cudaGetSymbolAddress((void**)&Kf, g_Kf);
    cudaGetSymbolAddress((void**)&Vf, g_Vf);

    cudaFuncSetAttribute(mma_gemm, cudaFuncAttributeMaxDynamicSharedMemorySize,
                         MG_SMEM);
    cudaFuncSetAttribute(attn9, cudaFuncAttributeMaxDynamicSharedMemorySize,
                         ATTN_SMEM);

    // -------- prep: ALL fp32->fp16 conversions in one launch --------
    {
        PrepSet p;
        const float* wsrc[8] = { Wq, Wk, Wv, Wq_add, Wk_add, Wv_add, Wo, Wo_add };
        for (int i = 0; i < 8; i++) {
            p.src[i] = wsrc[i];
            p.dst[i] = Whb + (size_t)i * WELEMS;
            p.n4[i]  = (int)(WELEMS / 4);
        }
        p.src[8] = hidden; p.dst[8] = Af;                          p.n4[8] = 1024 * DMODEL / 4;
        p.src[9] = enc;    p.dst[9] = Ef;                          p.n4[9] = STXT * DMODEL / 4;
        p.src[10] = cv;    p.dst[10] = Vf + (size_t)1280 * DMODEL; p.n4[10] = 3072 * DMODEL / 4;
        prep<<<dim3((int)(WELEMS / 4 / 512), 11), 256>>>(p);
    }

    // -------- QKV projections: ONE launch, fp16 outputs --------
    {
        TGemmSet g;
        for (int z = 0; z < 3; z++) {
            g.a[z] = Af;
            g.w[z] = Whb + (size_t)z * WELEMS;
            g.ny[z] = 8;
            g.a[z + 3] = Ef;
            g.w[z + 3] = Whb + (size_t)(z + 3) * WELEMS;
            g.ny[z + 3] = 2;
        }
        g.b[0] = bq; g.b[1] = bk; g.b[2] = bv;
        g.b[3] = bq_add; g.b[4] = bk_add; g.b[5] = bv_add;
        g.c[0] = Qp + (size_t)256 * DMODEL;
        g.c[1] = Kp + (size_t)256 * DMODEL;
        g.c[2] = Vf + (size_t)256 * DMODEL;
        g.c[3] = Qp; g.c[4] = Kp; g.c[5] = Vf;
        for (int z = 0; z < 6; z++) g.hout[z] = 1;
        mma_gemm<<<dim3(24, 8, 6), 256, MG_SMEM>>>(g);
    }

    // -------- fused RMSNorm + RoPE for Q and K (one launch) --------
    // qscale = 1/sqrt(128) * log2(e): base-2 softmax domain
    {
        const float qscale = 0.08838834764831845f * 1.4426950408889634f;
        int tot = (LQ + SKV) * NHEAD;
        normrope_qk<<<(tot + 7) / 8, dim3(32, 8)>>>(
            Qp, Kp, ck, naqw, nqw, nakw, nkw,
            tcos, tsin, icos, isin, qscale,
            (__half2*)Af, (__half2*)Kf);
    }

    // -------- attention: Q from Af, O back into Af --------
    attn9<<<dim3(LQ / 128, NHEAD), ATHREADS, ATTN_SMEM>>>(
        Af, Kf, Vf, mask, Af);

    // -------- output projections: ONE launch, fp32 outputs --------
    {
        TGemmSet g;
        g.a[0] = Af + (size_t)256 * DMODEL;
        g.w[0] = Whb + 6 * WELEMS;
        g.b[0] = bo;      g.c[0] = out;
        g.ny[0] = 8;
        g.a[1] = Af;
        g.w[1] = Whb + 7 * WELEMS;
        g.b[1] = bo_add;  g.c[1] = out + (size_t)1024 * DMODEL;
        g.ny[1] = 2;
        for (int z = 2; z < 6; z++) {
            g.a[z] = Af;
            g.w[z] = Whb;
            g.b[z] = bo; g.c[z] = out; g.ny[z] = 0;
        }
        for (int z = 0; z < 6; z++) g.hout[z] = 0;
        mma_gemm<<<dim3(24, 8, 2), 256, MG_SMEM>>>(g);
    }
}